// round 4
// baseline (speedup 1.0000x reference)
#include <cuda_runtime.h>
#include <cuda_bf16.h>
#include <cstdint>

#define B    64
#define HDIM 1024
#define SDIM 2048
#define VDIM 23262
#define EDIM 300
#define G4   4096          // 4*H
#define KCAT (HDIM + EDIM) // 1324

typedef unsigned long long ull;

// ---------------- scratch (static device globals; no allocation) ----------------
__device__ float g_q[B * HDIM];
__device__ float g_pm[B * 64];
__device__ float g_pl[B * 64];
__device__ float g_pacc[(size_t)B * 64 * HDIM];
__device__ float g_catA[B * 2 * HDIM];            // [context | h0]
__device__ float g_catB[B * KCAT];                // [ctx_hat | embedded]
__device__ float g_gates[B * G4];
__device__ float g_hN[B * HDIM];
__device__ float g_part[(size_t)4 * 1024 * 1024]; // split-K partials

// ---------------- packed f32x2 helpers (fp32 GEMM for q) ----------------
__device__ __forceinline__ void ffma2(ull& d, ull a, ull w) {
    asm("fma.rn.f32x2 %0, %1, %2, %0;" : "+l"(d) : "l"(a), "l"(w));
}
__device__ __forceinline__ ull pack_dup(float x) {
    ull r; asm("mov.b64 %0, {%1, %1};" : "=l"(r) : "f"(x)); return r;
}
__device__ __forceinline__ float2 unpack2(ull v) {
    float2 r; asm("mov.b64 {%0, %1}, %2;" : "=f"(r.x), "=f"(r.y) : "l"(v)); return r;
}

// ---------------- embedding gather into catB[:, H:H+E] ----------------
__global__ void k_embed(const int* __restrict__ tokens, const float* __restrict__ emb) {
    int b = blockIdx.x;
    int t = tokens[b];
    for (int e = threadIdx.x; e < EDIM; e += blockDim.x)
        g_catB[b * KCAT + HDIM + e] = emb[(size_t)t * EDIM + e];
}

// ================= HMMA bf16-split GEMM =================
// C[64, N] = A1[64,K1] @ W1[N,K1]^T (+ A2[64,K2] @ W2[N,K2]^T)
// fp32 -> hi/lo bf16 split; D += Ah*Wh + Ah*Wl + Al*Wh via mma.m16n8k16.
// K chunked by 64 into SW128-swizzled smem. Software-pipelined LDG staging.

__device__ __forceinline__ uint32_t swoff(uint32_t row, uint32_t kb) {
    uint32_t o = row * 128 + kb;
    return o ^ ((o >> 3) & 0x70);
}

__device__ __forceinline__ void ldblk16(const float* p, bool rv, int krem, float* v) {
    if (rv && krem >= 16) {
#pragma unroll
        for (int c = 0; c < 4; c++) {
            float4 t = *(const float4*)(p + 4 * c);
            v[4 * c + 0] = t.x; v[4 * c + 1] = t.y; v[4 * c + 2] = t.z; v[4 * c + 3] = t.w;
        }
    } else {
#pragma unroll
        for (int j = 0; j < 16; j++) v[j] = (rv && j < krem) ? p[j] : 0.f;
    }
}

__device__ __forceinline__ void stblk16(const float* v, char* dh, char* dl,
                                        uint32_t row, uint32_t kb) {
    uint32_t hb[8], lb[8];
#pragma unroll
    for (int j = 0; j < 8; j++) {
        float x0 = v[2 * j], x1 = v[2 * j + 1];
        __nv_bfloat16 a0 = __float2bfloat16(x0);
        __nv_bfloat16 a1 = __float2bfloat16(x1);
        __nv_bfloat16 c0 = __float2bfloat16(x0 - __bfloat162float(a0));
        __nv_bfloat16 c1 = __float2bfloat16(x1 - __bfloat162float(a1));
        hb[j] = ((uint32_t)__bfloat16_as_ushort(a1) << 16) | __bfloat16_as_ushort(a0);
        lb[j] = ((uint32_t)__bfloat16_as_ushort(c1) << 16) | __bfloat16_as_ushort(c0);
    }
    uint32_t o0 = swoff(row, kb), o1 = swoff(row, kb + 16);
    *(uint4*)(dh + o0) = make_uint4(hb[0], hb[1], hb[2], hb[3]);
    *(uint4*)(dh + o1) = make_uint4(hb[4], hb[5], hb[6], hb[7]);
    *(uint4*)(dl + o0) = make_uint4(lb[0], lb[1], lb[2], lb[3]);
    *(uint4*)(dl + o1) = make_uint4(lb[4], lb[5], lb[6], lb[7]);
}

__device__ __forceinline__ void hmma(float* c, const uint32_t* a, const uint32_t* b) {
    asm volatile("mma.sync.aligned.m16n8k16.row.col.f32.bf16.bf16.f32 "
                 "{%0,%1,%2,%3}, {%4,%5,%6,%7}, {%8,%9}, {%0,%1,%2,%3};"
                 : "+f"(c[0]), "+f"(c[1]), "+f"(c[2]), "+f"(c[3])
                 : "r"(a[0]), "r"(a[1]), "r"(a[2]), "r"(a[3]), "r"(b[0]), "r"(b[1]));
}

// NT = 128 (MF=2) or 64 (MF=1). NF = 4 always (warp covers 32 n).
template <int NT>
__global__ __launch_bounds__(256, 1) void k_mma(
    const float* __restrict__ A1, int K1, const float* __restrict__ W1,
    const float* __restrict__ A2, int K2, const float* __restrict__ W2,
    float* __restrict__ C, int ldc, int N, int nsl,
    const float* __restrict__ bias1, const float* __restrict__ bias2,
    int act, float* __restrict__ part)
{
    constexpr int MF   = (NT == 128) ? 2 : 1;
    constexpr int NWR  = NT * 128;     // W tile bytes per split
    extern __shared__ char sm[];
    char* sAh = sm;
    char* sAl = sm + 8192;
    char* sWh = sm + 16384;
    char* sWl = sm + 16384 + NWR;

    int tid  = threadIdx.x;
    int wid  = tid >> 5, lane = tid & 31;
    int g    = lane >> 2, tig = lane & 3;
    int tig4 = tig * 4;
    int n0   = blockIdx.x * NT;

    int mbase = (NT == 128) ? (wid >> 2) * 32 : (wid >> 1) * 16;
    int nbase = (NT == 128) ? (wid & 3) * 32  : (wid & 1) * 32;

    int nc1 = (K1 + 63) >> 6;
    int nc2 = W2 ? ((K2 + 63) >> 6) : 0;
    int NC  = nc1 + nc2;
    int per = (NC + nsl - 1) / nsl;
    int cs  = blockIdx.y * per;
    int ce  = min(NC, cs + per);

    float acc[MF][4][4];
#pragma unroll
    for (int mf = 0; mf < MF; mf++)
#pragma unroll
        for (int nf = 0; nf < 4; nf++)
#pragma unroll
            for (int j = 0; j < 4; j++) acc[mf][nf][j] = 0.f;

    // staging registers
    float areg[16];
    float wreg[(NT == 128) ? 32 : 16];

    // thread load mapping
    int arow = tid >> 2, aqd = tid & 3;                        // A: 16 vals
    int wrow = (NT == 128) ? (tid >> 1) : (tid >> 2);          // W row
    int wkof = (NT == 128) ? (tid & 1) * 32 : (tid & 3) * 16;  // W k offset (vals)

    auto load_chunk = [&](int ci) {
        const float* Ac; const float* Wc; int Kc, kc;
        if (ci < nc1) { Ac = A1; Wc = W1; Kc = K1; kc = ci; }
        else          { Ac = A2; Wc = W2; Kc = K2; kc = ci - nc1; }
        int k0 = kc * 64;
        ldblk16(Ac + (size_t)arow * Kc + k0 + aqd * 16, true,
                Kc - (k0 + aqd * 16), areg);
        bool rv = (n0 + wrow) < N;
        const float* wp = Wc + (size_t)(n0 + wrow) * Kc + k0 + wkof;
        ldblk16(wp, rv, Kc - (k0 + wkof), wreg);
        if (NT == 128)
            ldblk16(wp + 16, rv, Kc - (k0 + wkof + 16), wreg + 16);
    };

    if (cs < ce) load_chunk(cs);

    for (int ci = cs; ci < ce; ci++) {
        __syncthreads();   // previous mma done reading smem
        stblk16(areg, sAh, sAl, (uint32_t)arow, (uint32_t)(aqd * 32));
        stblk16(wreg, sWh, sWl, (uint32_t)wrow, (uint32_t)(wkof * 2));
        if (NT == 128)
            stblk16(wreg + 16, sWh, sWl, (uint32_t)wrow, (uint32_t)(wkof * 2 + 32));
        __syncthreads();
        if (ci + 1 < ce) load_chunk(ci + 1);   // hide LDG under MMA

#pragma unroll
        for (int ks = 0; ks < 4; ks++) {
            uint32_t kb = ks * 32;
            uint32_t ah[MF][4], al[MF][4];
#pragma unroll
            for (int mf = 0; mf < MF; mf++) {
                uint32_t r0 = mbase + mf * 16 + g, r1 = r0 + 8;
                ah[mf][0] = *(const uint32_t*)(sAh + swoff(r0, kb + tig4));
                ah[mf][1] = *(const uint32_t*)(sAh + swoff(r1, kb + tig4));
                ah[mf][2] = *(const uint32_t*)(sAh + swoff(r0, kb + 16 + tig4));
                ah[mf][3] = *(const uint32_t*)(sAh + swoff(r1, kb + 16 + tig4));
                al[mf][0] = *(const uint32_t*)(sAl + swoff(r0, kb + tig4));
                al[mf][1] = *(const uint32_t*)(sAl + swoff(r1, kb + tig4));
                al[mf][2] = *(const uint32_t*)(sAl + swoff(r0, kb + 16 + tig4));
                al[mf][3] = *(const uint32_t*)(sAl + swoff(r1, kb + 16 + tig4));
            }
            uint32_t bh[4][2], bl[4][2];
#pragma unroll
            for (int nf = 0; nf < 4; nf++) {
                uint32_t rn = nbase + nf * 8 + g;
                bh[nf][0] = *(const uint32_t*)(sWh + swoff(rn, kb + tig4));
                bh[nf][1] = *(const uint32_t*)(sWh + swoff(rn, kb + 16 + tig4));
                bl[nf][0] = *(const uint32_t*)(sWl + swoff(rn, kb + tig4));
                bl[nf][1] = *(const uint32_t*)(sWl + swoff(rn, kb + 16 + tig4));
            }
#pragma unroll
            for (int mf = 0; mf < MF; mf++)
#pragma unroll
                for (int nf = 0; nf < 4; nf++) {
                    hmma(acc[mf][nf], ah[mf], bh[nf]);
                    hmma(acc[mf][nf], ah[mf], bl[nf]);
                    hmma(acc[mf][nf], al[mf], bh[nf]);
                }
        }
    }

    // ---- epilogue ----
#pragma unroll
    for (int mf = 0; mf < MF; mf++)
#pragma unroll
        for (int nf = 0; nf < 4; nf++) {
            int row = mbase + mf * 16 + g;
            int n   = n0 + nbase + nf * 8 + tig * 2;
            float2 v0 = make_float2(acc[mf][nf][0], acc[mf][nf][1]);
            float2 v1 = make_float2(acc[mf][nf][2], acc[mf][nf][3]);
            if (nsl == 1) {
                if (n < N) {
                    if (bias1) { v0.x += bias1[n]; v0.y += bias1[n + 1];
                                 v1.x += bias1[n]; v1.y += bias1[n + 1]; }
                    if (bias2) { v0.x += bias2[n]; v0.y += bias2[n + 1];
                                 v1.x += bias2[n]; v1.y += bias2[n + 1]; }
                    if (act) { v0.x = tanhf(v0.x); v0.y = tanhf(v0.y);
                               v1.x = tanhf(v1.x); v1.y = tanhf(v1.y); }
                    *(float2*)&C[(size_t)row * ldc + n]       = v0;
                    *(float2*)&C[(size_t)(row + 8) * ldc + n] = v1;
                }
            } else {
                if (n < N) {
                    size_t base = ((size_t)blockIdx.y * B) * (size_t)N;
                    *(float2*)&part[base + (size_t)row * N + n]       = v0;
                    *(float2*)&part[base + (size_t)(row + 8) * N + n] = v1;
                }
            }
        }
}

// ---------------- fp32 skinny GEMM (q projection; W [K,N] n-major) ----------------
template <bool WKMAJOR, bool DIRECT>
__global__ __launch_bounds__(256) void k_gemm(
    const float* __restrict__ A, int lda,
    const float* __restrict__ W, int ldw,
    float* __restrict__ C, int ldc,
    int N, int K, int nsl, int slice_base,
    const float* __restrict__ bias)
{
    __shared__ float sW[32][128];
    __shared__ float sA[32][64];
    int tid = threadIdx.x;
    int tx = tid & 31, ty = tid >> 5;
    int n0 = blockIdx.x * 128;

    int nk32 = (K + 31) >> 5;
    int per  = (nk32 + nsl - 1) / nsl;
    int k0s  = blockIdx.y * per * 32;
    int k0e  = min(K, (int)(blockIdx.y + 1) * per * 32);

    ull acc[8][2];
#pragma unroll
    for (int j = 0; j < 8; j++) { acc[j][0] = 0ULL; acc[j][1] = 0ULL; }

    for (int k0 = k0s; k0 < k0e; k0 += 32) {
        bool full = (k0 + 32 <= K);
        {
            int bb = tid >> 2;
            int kq = (tid & 3) * 4;
            const float* ap = A + (size_t)bb * lda + k0;
#pragma unroll
            for (int c = 0; c < 2; c++) {
                int off = kq + c * 16;
                float4 v;
                if (full) v = *(const float4*)(ap + off);
                else {
                    v.x = (k0 + off + 0 < K) ? ap[off + 0] : 0.f;
                    v.y = (k0 + off + 1 < K) ? ap[off + 1] : 0.f;
                    v.z = (k0 + off + 2 < K) ? ap[off + 2] : 0.f;
                    v.w = (k0 + off + 3 < K) ? ap[off + 3] : 0.f;
                }
                sA[off + 0][bb] = v.x; sA[off + 1][bb] = v.y;
                sA[off + 2][bb] = v.z; sA[off + 3][bb] = v.w;
            }
        }
        if (WKMAJOR) {
            int n = tid >> 1, half = (tid & 1) * 16;
            bool nv = (n0 + n) < N;
            const float* wp = W + (size_t)(n0 + n) * ldw + k0 + half;
#pragma unroll
            for (int c = 0; c < 4; c++) {
                int off = half + c * 4;
                float4 v;
                if (nv && full) v = *(const float4*)(wp + c * 4);
                else {
                    v.x = (nv && k0 + off + 0 < K) ? wp[c * 4 + 0] : 0.f;
                    v.y = (nv && k0 + off + 1 < K) ? wp[c * 4 + 1] : 0.f;
                    v.z = (nv && k0 + off + 2 < K) ? wp[c * 4 + 2] : 0.f;
                    v.w = (nv && k0 + off + 3 < K) ? wp[c * 4 + 3] : 0.f;
                }
                sW[off + 0][n] = v.x; sW[off + 1][n] = v.y;
                sW[off + 2][n] = v.z; sW[off + 3][n] = v.w;
            }
        } else {
            int kk = tid >> 3;
            int k  = k0 + kk;
            bool kv = k < K;
            const float* wp = W + (size_t)k * ldw + n0;
#pragma unroll
            for (int c = 0; c < 4; c++) {
                int nn = (tid & 7) * 4 + c * 32;
                float4 v;
                if (kv && (n0 + nn + 3) < N) v = *(const float4*)(wp + nn);
                else {
                    v.x = (kv && n0 + nn + 0 < N) ? wp[nn + 0] : 0.f;
                    v.y = (kv && n0 + nn + 1 < N) ? wp[nn + 1] : 0.f;
                    v.z = (kv && n0 + nn + 2 < N) ? wp[nn + 2] : 0.f;
                    v.w = (kv && n0 + nn + 3 < N) ? wp[nn + 3] : 0.f;
                }
                *(float4*)&sW[kk][nn] = v;
            }
        }
        __syncthreads();

#pragma unroll 8
        for (int kk = 0; kk < 32; kk++) {
            float4 a0 = *(const float4*)&sA[kk][ty * 8];
            float4 a1 = *(const float4*)&sA[kk][ty * 8 + 4];
            const ull* wp2 = (const ull*)&sW[kk][tx * 4];
            ull w0 = wp2[0], w1 = wp2[1];
            ull ad[8];
            ad[0] = pack_dup(a0.x); ad[1] = pack_dup(a0.y);
            ad[2] = pack_dup(a0.z); ad[3] = pack_dup(a0.w);
            ad[4] = pack_dup(a1.x); ad[5] = pack_dup(a1.y);
            ad[6] = pack_dup(a1.z); ad[7] = pack_dup(a1.w);
#pragma unroll
            for (int j = 0; j < 8; j++) { ffma2(acc[j][0], ad[j], w0); ffma2(acc[j][1], ad[j], w1); }
        }
        __syncthreads();
    }

#pragma unroll
    for (int j = 0; j < 8; j++) {
        int bb = ty * 8 + j;
#pragma unroll
        for (int p = 0; p < 2; p++) {
            float2 v = unpack2(acc[j][p]);
            int n = n0 + tx * 4 + p * 2;
            if (DIRECT) {
                if (bias) { v.x += bias[n]; if (n + 1 < N) v.y += bias[n + 1]; }
                if (n + 1 < N) *(float2*)&C[(size_t)bb * ldc + n] = v;
                else if (n < N) C[(size_t)bb * ldc + n] = v.x;
            } else {
                size_t base = ((size_t)(slice_base + blockIdx.y) * B + bb) * (size_t)N;
                if (n + 1 < N) *(float2*)&C[base + n] = v;
                else if (n < N) C[base + n] = v.x;
            }
        }
    }
}

__global__ void k_scomb(const float* __restrict__ part, int N, int nsl,
                        const float* __restrict__ b1, const float* __restrict__ b2,
                        int act, float* __restrict__ dst, int ldd)
{
    int idx = blockIdx.x * blockDim.x + threadIdx.x;
    if (idx >= B * N) return;
    int b = idx / N, n = idx % N;
    float v = 0.f;
    if (b1) v += b1[n];
    if (b2) v += b2[n];
    for (int s = 0; s < nsl; s++) v += part[((size_t)s * B + b) * (size_t)N + n];
    if (act) v = tanhf(v);
    dst[(size_t)b * ldd + n] = v;
}

// ---------------- fused attention (single read of encoder_out) ----------------
__global__ __launch_bounds__(256) void k_attn(const float* __restrict__ enc)
{
    int b = blockIdx.y;
    int warp = threadIdx.x >> 5, lane = threadIdx.x & 31;
    int wg = blockIdx.x * 8 + warp;

    const float4* qp = (const float4*)(g_q + (size_t)b * HDIM);
    float4 qv[8];
#pragma unroll
    for (int j = 0; j < 8; j++) qv[j] = qp[j * 32 + lane];

    float4 av[8];
#pragma unroll
    for (int j = 0; j < 8; j++) av[j] = make_float4(0.f, 0.f, 0.f, 0.f);
    float m = -1e30f, l = 0.f;

    int s0 = wg * 32;
    for (int r = 0; r < 32; r++) {
        const float4* row = (const float4*)(enc + ((size_t)(s0 + r) * B + b) * HDIM);
        float4 e[8];
#pragma unroll
        for (int j = 0; j < 8; j++) e[j] = row[j * 32 + lane];
        float d = 0.f;
#pragma unroll
        for (int j = 0; j < 8; j++)
            d += e[j].x * qv[j].x + e[j].y * qv[j].y + e[j].z * qv[j].z + e[j].w * qv[j].w;
#pragma unroll
        for (int off = 16; off > 0; off >>= 1)
            d += __shfl_xor_sync(0xffffffffu, d, off);

        float mn  = fmaxf(m, d);
        float fac = __expf(m - mn);
        float p   = __expf(d - mn);
        l = l * fac + p;
        m = mn;
#pragma unroll
        for (int j = 0; j < 8; j++) {
            av[j].x = av[j].x * fac + p * e[j].x;
            av[j].y = av[j].y * fac + p * e[j].y;
            av[j].z = av[j].z * fac + p * e[j].z;
            av[j].w = av[j].w * fac + p * e[j].w;
        }
    }
    int pi = b * 64 + wg;
    if (lane == 0) { g_pm[pi] = m; g_pl[pi] = l; }
    float4* pa = (float4*)(g_pacc + (size_t)pi * HDIM);
#pragma unroll
    for (int j = 0; j < 8; j++) pa[j * 32 + lane] = av[j];
}

__global__ void k_attn_comb(const float* __restrict__ h0)
{
    int b = blockIdx.x, t = threadIdx.x;
    float M = -1e30f;
    for (int c = 0; c < 64; c++) M = fmaxf(M, g_pm[b * 64 + c]);
    float lsum = 0.f;
    float4 ctx = make_float4(0.f, 0.f, 0.f, 0.f);
    for (int c = 0; c < 64; c++) {
        float fac = __expf(g_pm[b * 64 + c] - M);
        lsum += fac * g_pl[b * 64 + c];
        float4 a = *(const float4*)(g_pacc + (size_t)(b * 64 + c) * HDIM + t * 4);
        ctx.x += fac * a.x; ctx.y += fac * a.y;
        ctx.z += fac * a.z; ctx.w += fac * a.w;
    }
    float inv = 1.f / lsum;
    float4* dA = (float4*)(g_catA + (size_t)b * 2 * HDIM);
    dA[t] = make_float4(ctx.x * inv, ctx.y * inv, ctx.z * inv, ctx.w * inv);
    const float4* h4 = (const float4*)(h0 + (size_t)b * HDIM);
    dA[256 + t] = h4[t];
}

__global__ void k_lstm(const float* __restrict__ c0, float* __restrict__ out)
{
    int b = blockIdx.x, t = threadIdx.x;
    const float* g = g_gates + (size_t)b * G4;
#pragma unroll
    for (int c = 0; c < 4; c++) {
        int h = t * 4 + c;
        float gi = g[h], gf = g[HDIM + h], gg = g[2 * HDIM + h], go = g[3 * HDIM + h];
        float si = 1.f / (1.f + __expf(-gi));
        float sf = 1.f / (1.f + __expf(-gf));
        float so = 1.f / (1.f + __expf(-go));
        float cn = sf * c0[(size_t)b * HDIM + h] + si * tanhf(gg);
        float hn = so * tanhf(cn);
        g_hN[(size_t)b * HDIM + h] = hn;
        out[(size_t)B * VDIM + (size_t)b * HDIM + h] = hn;
        out[(size_t)B * VDIM + (size_t)B * HDIM + (size_t)b * HDIM + h] = cn;
    }
}

// ---------------- host launch ----------------
extern "C" void kernel_launch(void* const* d_in, const int* in_sizes, int n_in,
                              void* d_out, int out_size)
{
    const int*   tokens = (const int*)  d_in[0];
    const float* enc    = (const float*)d_in[1];
    const float* h0     = (const float*)d_in[2];
    const float* c0     = (const float*)d_in[3];
    const float* emb    = (const float*)d_in[4];
    const float* W_in   = (const float*)d_in[5];
    const float* W_out  = (const float*)d_in[6];
    const float* W_ih   = (const float*)d_in[7];
    const float* W_hh   = (const float*)d_in[8];
    const float* b_ih   = (const float*)d_in[9];
    const float* b_hh   = (const float*)d_in[10];
    const float* W_gen  = (const float*)d_in[11];
    const float* b_gen  = (const float*)d_in[12];
    float* out = (float*)d_out;

    float *part, *qbuf, *catA, *catB, *gates, *hN;
    cudaGetSymbolAddress((void**)&part,  g_part);
    cudaGetSymbolAddress((void**)&qbuf,  g_q);
    cudaGetSymbolAddress((void**)&catA,  g_catA);
    cudaGetSymbolAddress((void**)&catB,  g_catB);
    cudaGetSymbolAddress((void**)&gates, g_gates);
    cudaGetSymbolAddress((void**)&hN,    g_hN);

    const int SM128 = 16384 + 2 * 128 * 128;  // 49152
    const int SM64  = 16384 + 2 * 64 * 128;   // 32768
    cudaFuncSetAttribute(k_mma<128>, cudaFuncAttributeMaxDynamicSharedMemorySize, SM128);
    cudaFuncSetAttribute(k_mma<64>,  cudaFuncAttributeMaxDynamicSharedMemorySize, SM64);

    // embedding gather
    k_embed<<<B, 128>>>(tokens, emb);

    // q = h0 @ W_in  (W_in [K,N] n-major), split-K 16 on fp32 path
    k_gemm<false, false><<<dim3(8, 16), 256>>>(h0, HDIM, W_in, HDIM,
                                               part, 0, HDIM, HDIM, 16, 0, nullptr);
    k_scomb<<<(B * HDIM + 255) / 256, 256>>>(part, HDIM, 16, nullptr, nullptr, 0, qbuf, HDIM);

    // fused single-pass attention
    k_attn<<<dim3(8, B), 256>>>(enc);
    k_attn_comb<<<B, 256>>>(h0);

    // ctx_hat = tanh(catA @ W_out^T) -> catB[:, 0:H]  (HMMA, NT=64, split-K 4)
    k_mma<64><<<dim3(HDIM / 64, 4), 256, SM64>>>(catA, 2 * HDIM, W_out,
                                                 nullptr, 0, nullptr,
                                                 nullptr, 0, HDIM, 4,
                                                 nullptr, nullptr, 0, part);
    k_scomb<<<(B * HDIM + 255) / 256, 256>>>(part, HDIM, 4, nullptr, nullptr, 1, catB, KCAT);

    // gates = catB @ W_ih^T + h0 @ W_hh^T + b_ih + b_hh  (HMMA dual, NT=64)
    k_mma<64><<<dim3(G4 / 64, 1), 256, SM64>>>(catB, KCAT, W_ih,
                                               h0, HDIM, W_hh,
                                               gates, G4, G4, 1,
                                               b_ih, b_hh, 0, nullptr);

    // LSTM cell -> hN, cN
    k_lstm<<<B, 256>>>(c0, out);

    // logits = hN @ W_gen^T + b_gen  (HMMA, NT=128, direct)
    k_mma<128><<<dim3((VDIM + 127) / 128, 1), 256, SM128>>>(hN, HDIM, W_gen,
                                                            nullptr, 0, nullptr,
                                                            out, VDIM, VDIM, 1,
                                                            b_gen, nullptr, 0, nullptr);
}

// round 5
// speedup vs baseline: 1.1154x; 1.1154x over previous
#include <cuda_runtime.h>
#include <cuda_bf16.h>
#include <cstdint>

#define B    64
#define HDIM 1024
#define SDIM 2048
#define VDIM 23262
#define EDIM 300
#define G4   4096          // 4*H
#define KCAT (HDIM + EDIM) // 1324

typedef unsigned long long ull;

// ---------------- scratch (static device globals; no allocation) ----------------
__device__ float g_q[B * HDIM];
__device__ float g_pm[B * 64];
__device__ float g_pl[B * 64];
__device__ float g_pacc[(size_t)B * 64 * HDIM];
__device__ float g_catA[B * 2 * HDIM];            // [context | h0]
__device__ float g_catB[B * KCAT];                // [ctx_hat | embedded]
__device__ float g_gates[B * G4];
__device__ float g_hN[B * HDIM];
__device__ float g_part[(size_t)4 * 1024 * 1024]; // split-K partials

// ---------------- packed f32x2 helpers (fp32 GEMM for q) ----------------
__device__ __forceinline__ void ffma2(ull& d, ull a, ull w) {
    asm("fma.rn.f32x2 %0, %1, %2, %0;" : "+l"(d) : "l"(a), "l"(w));
}
__device__ __forceinline__ ull pack_dup(float x) {
    ull r; asm("mov.b64 %0, {%1, %1};" : "=l"(r) : "f"(x)); return r;
}
__device__ __forceinline__ float2 unpack2(ull v) {
    float2 r; asm("mov.b64 {%0, %1}, %2;" : "=f"(r.x), "=f"(r.y) : "l"(v)); return r;
}

// ---------------- embedding gather into catB[:, H:H+E] ----------------
__global__ void k_embed(const int* __restrict__ tokens, const float* __restrict__ emb) {
    int b = blockIdx.x;
    int t = tokens[b];
    for (int e = threadIdx.x; e < EDIM; e += blockDim.x)
        g_catB[b * KCAT + HDIM + e] = emb[(size_t)t * EDIM + e];
}

// ================= HMMA bf16-split GEMM (NT=64) =================
// C[64, N] = A1[64,K1] @ W1[N,K1]^T (+ A2 @ W2^T). hi = truncated bf16 (PRMT),
// lo = bf16(x - hi): D += Ah*Wh + Ah*Wl + Al*Wh. K chunks of 64, double-buffered,
// ldmatrix fragment loads, 2 CTAs/SM.

__device__ __forceinline__ uint32_t swzf(uint32_t o) { return o ^ ((o >> 3) & 0x70); }

__device__ __forceinline__ void cvt16(const float* v, uint32_t* h, uint32_t* l) {
#pragma unroll
    for (int j = 0; j < 8; j++) {
        uint32_t u0 = __float_as_uint(v[2 * j]);
        uint32_t u1 = __float_as_uint(v[2 * j + 1]);
        asm("prmt.b32 %0, %1, %2, 0x7632;" : "=r"(h[j]) : "r"(u0), "r"(u1));
        float l0 = v[2 * j]     - __uint_as_float(u0 & 0xFFFF0000u);
        float l1 = v[2 * j + 1] - __uint_as_float(u1 & 0xFFFF0000u);
        asm("cvt.rn.bf16x2.f32 %0, %1, %2;" : "=r"(l[j]) : "f"(l1), "f"(l0));
    }
}

__device__ __forceinline__ void ldsm4(uint32_t& r0, uint32_t& r1, uint32_t& r2, uint32_t& r3,
                                      uint32_t addr) {
    asm volatile("ldmatrix.sync.aligned.m8n8.x4.shared.b16 {%0,%1,%2,%3}, [%4];"
                 : "=r"(r0), "=r"(r1), "=r"(r2), "=r"(r3) : "r"(addr));
}

__device__ __forceinline__ void hmma(float* c, const uint32_t* a, const uint32_t* b) {
    asm volatile("mma.sync.aligned.m16n8k16.row.col.f32.bf16.bf16.f32 "
                 "{%0,%1,%2,%3}, {%4,%5,%6,%7}, {%8,%9}, {%0,%1,%2,%3};"
                 : "+f"(c[0]), "+f"(c[1]), "+f"(c[2]), "+f"(c[3])
                 : "r"(a[0]), "r"(a[1]), "r"(a[2]), "r"(a[3]), "r"(b[0]), "r"(b[1]));
}

__global__ __launch_bounds__(256, 2) void k_hmma(
    const float* __restrict__ A1, int K1, const float* __restrict__ W1,
    const float* __restrict__ A2, int K2, const float* __restrict__ W2,
    float* __restrict__ C, int ldc, int N, int nsl,
    const float* __restrict__ bias1, const float* __restrict__ bias2,
    int act, float* __restrict__ part)
{
    extern __shared__ char sm[];
    // per buffer (32768B): sAh +0, sAl +8192, sWh +16384, sWl +24576
    int tid = threadIdx.x, wid = tid >> 5, lane = tid & 31;
    int g = lane >> 2, tig = lane & 3;
    int n0 = blockIdx.x * 64;
    int mbase = (wid >> 1) * 16, nbase = (wid & 1) * 32;

    int nc1 = (K1 + 63) >> 6;
    int nc2 = W2 ? ((K2 + 63) >> 6) : 0;
    int NC  = nc1 + nc2;
    int per = (NC + nsl - 1) / nsl;
    int cs  = blockIdx.y * per;
    int ce  = min(NC, cs + per);

    uint32_t smbase = (uint32_t)__cvta_generic_to_shared(sm);

    // ldmatrix per-lane address components
    int la = lane & 7, lb3 = (lane >> 3) & 1, lb4 = (lane >> 4) & 1;
    uint32_t rawA  = (uint32_t)(mbase + la + lb3 * 8) * 128 + (uint32_t)lb4 * 16;
    uint32_t xorA  = (rawA >> 3) & 0x70;
    uint32_t rawB0 = (uint32_t)(nbase + la + lb4 * 8) * 128 + (uint32_t)lb3 * 16;
    uint32_t rawB1 = rawB0 + 16 * 128;
    uint32_t xorB0 = (rawB0 >> 3) & 0x70;
    uint32_t xorB1 = (rawB1 >> 3) & 0x70;

    // fill mapping: thread covers row=tid>>2 (0..63), 16 cols at (tid&3)*16
    int frow = tid >> 2, fqd = tid & 3;

    float acc[4][4];
#pragma unroll
    for (int nf = 0; nf < 4; nf++)
#pragma unroll
        for (int j = 0; j < 4; j++) acc[nf][j] = 0.f;

    float stA[16], stW[16];

    auto ldg_chunk = [&](int ci) {
        const float* Ac; const float* Wc; int Kc, kc;
        if (ci < nc1) { Ac = A1; Wc = W1; Kc = K1; kc = ci; }
        else          { Ac = A2; Wc = W2; Kc = K2; kc = ci - nc1; }
        int k0 = kc * 64 + fqd * 16;
        {
            const float* p = Ac + (size_t)frow * Kc + k0;
            if (k0 + 16 <= Kc) {
#pragma unroll
                for (int c = 0; c < 4; c++) {
                    float4 t = *(const float4*)(p + 4 * c);
                    stA[4 * c] = t.x; stA[4 * c + 1] = t.y; stA[4 * c + 2] = t.z; stA[4 * c + 3] = t.w;
                }
            } else {
#pragma unroll
                for (int j = 0; j < 16; j++) stA[j] = (k0 + j < Kc) ? p[j] : 0.f;
            }
        }
        {
            bool rv = (n0 + frow) < N;
            const float* p = Wc + (size_t)(n0 + frow) * Kc + k0;
            if (rv && k0 + 16 <= Kc) {
#pragma unroll
                for (int c = 0; c < 4; c++) {
                    float4 t = *(const float4*)(p + 4 * c);
                    stW[4 * c] = t.x; stW[4 * c + 1] = t.y; stW[4 * c + 2] = t.z; stW[4 * c + 3] = t.w;
                }
            } else {
#pragma unroll
                for (int j = 0; j < 16; j++) stW[j] = (rv && k0 + j < Kc) ? p[j] : 0.f;
            }
        }
    };

    uint32_t so0 = swzf((uint32_t)frow * 128 + (uint32_t)fqd * 32);
    uint32_t so1 = swzf((uint32_t)frow * 128 + (uint32_t)fqd * 32 + 16);

    auto sts_chunk = [&](int buf) {
        char* bb = sm + buf * 32768;
        uint32_t h[8], l[8];
        cvt16(stA, h, l);
        *(uint4*)(bb + so0)        = make_uint4(h[0], h[1], h[2], h[3]);
        *(uint4*)(bb + so1)        = make_uint4(h[4], h[5], h[6], h[7]);
        *(uint4*)(bb + 8192 + so0) = make_uint4(l[0], l[1], l[2], l[3]);
        *(uint4*)(bb + 8192 + so1) = make_uint4(l[4], l[5], l[6], l[7]);
        cvt16(stW, h, l);
        *(uint4*)(bb + 16384 + so0) = make_uint4(h[0], h[1], h[2], h[3]);
        *(uint4*)(bb + 16384 + so1) = make_uint4(h[4], h[5], h[6], h[7]);
        *(uint4*)(bb + 24576 + so0) = make_uint4(l[0], l[1], l[2], l[3]);
        *(uint4*)(bb + 24576 + so1) = make_uint4(l[4], l[5], l[6], l[7]);
    };

    if (cs < ce) { ldg_chunk(cs); sts_chunk(0); }
    __syncthreads();

    for (int ci = cs; ci < ce; ci++) {
        int buf = (ci - cs) & 1;
        if (ci + 1 < ce) ldg_chunk(ci + 1);   // LDG in flight under MMA

        uint32_t bufb = smbase + (uint32_t)buf * 32768;
#pragma unroll
        for (int ks = 0; ks < 4; ks++) {
            uint32_t kb = (uint32_t)ks * 32;
            uint32_t aA = bufb + ((rawA + kb) ^ xorA);
            uint32_t ah[4], al[4];
            ldsm4(ah[0], ah[1], ah[2], ah[3], aA);
            ldsm4(al[0], al[1], al[2], al[3], aA + 8192);
            uint32_t b0 = bufb + 16384 + ((rawB0 + kb) ^ xorB0);
            uint32_t b1 = bufb + 16384 + ((rawB1 + kb) ^ xorB1);
            uint32_t bh[8], bl[8];
            ldsm4(bh[0], bh[1], bh[2], bh[3], b0);
            ldsm4(bh[4], bh[5], bh[6], bh[7], b1);
            ldsm4(bl[0], bl[1], bl[2], bl[3], b0 + 8192);
            ldsm4(bl[4], bl[5], bl[6], bl[7], b1 + 8192);
#pragma unroll
            for (int nf = 0; nf < 4; nf++) {
                hmma(acc[nf], ah, &bh[nf * 2]);
                hmma(acc[nf], ah, &bl[nf * 2]);
                hmma(acc[nf], al, &bh[nf * 2]);
            }
        }
        if (ci + 1 < ce) sts_chunk(buf ^ 1);
        __syncthreads();
    }

    // ---- epilogue ----
#pragma unroll
    for (int nf = 0; nf < 4; nf++) {
        int row = mbase + g;
        int n   = n0 + nbase + nf * 8 + tig * 2;
        float2 v0 = make_float2(acc[nf][0], acc[nf][1]);
        float2 v1 = make_float2(acc[nf][2], acc[nf][3]);
        if (n < N) {
            if (nsl == 1) {
                if (bias1) { v0.x += bias1[n]; v0.y += bias1[n + 1];
                             v1.x += bias1[n]; v1.y += bias1[n + 1]; }
                if (bias2) { v0.x += bias2[n]; v0.y += bias2[n + 1];
                             v1.x += bias2[n]; v1.y += bias2[n + 1]; }
                if (act) { v0.x = tanhf(v0.x); v0.y = tanhf(v0.y);
                           v1.x = tanhf(v1.x); v1.y = tanhf(v1.y); }
                *(float2*)&C[(size_t)row * ldc + n]       = v0;
                *(float2*)&C[(size_t)(row + 8) * ldc + n] = v1;
            } else {
                size_t base = ((size_t)blockIdx.y * B) * (size_t)N;
                *(float2*)&part[base + (size_t)row * N + n]       = v0;
                *(float2*)&part[base + (size_t)(row + 8) * N + n] = v1;
            }
        }
    }
}

// ---------------- fp32 skinny GEMM (q projection; W [K,N] n-major) ----------------
__global__ __launch_bounds__(256) void k_gemm_nk(
    const float* __restrict__ A, int lda,
    const float* __restrict__ W, int ldw,
    float* __restrict__ C, int N, int K, int nsl)
{
    __shared__ float sW[32][128];
    __shared__ float sA[32][64];
    int tid = threadIdx.x;
    int tx = tid & 31, ty = tid >> 5;
    int n0 = blockIdx.x * 128;

    int nk32 = (K + 31) >> 5;
    int per  = (nk32 + nsl - 1) / nsl;
    int k0s  = blockIdx.y * per * 32;
    int k0e  = min(K, (int)(blockIdx.y + 1) * per * 32);

    ull acc[8][2];
#pragma unroll
    for (int j = 0; j < 8; j++) { acc[j][0] = 0ULL; acc[j][1] = 0ULL; }

    for (int k0 = k0s; k0 < k0e; k0 += 32) {
        {
            int bb = tid >> 2;
            int kq = (tid & 3) * 4;
            const float* ap = A + (size_t)bb * lda + k0;
#pragma unroll
            for (int c = 0; c < 2; c++) {
                int off = kq + c * 16;
                float4 v = *(const float4*)(ap + off);
                sA[off + 0][bb] = v.x; sA[off + 1][bb] = v.y;
                sA[off + 2][bb] = v.z; sA[off + 3][bb] = v.w;
            }
        }
        {
            int kk = tid >> 3;
            const float* wp = W + (size_t)(k0 + kk) * ldw + n0;
#pragma unroll
            for (int c = 0; c < 4; c++) {
                int nn = (tid & 7) * 4 + c * 32;
                *(float4*)&sW[kk][nn] = *(const float4*)(wp + nn);
            }
        }
        __syncthreads();

#pragma unroll 8
        for (int kk = 0; kk < 32; kk++) {
            float4 a0 = *(const float4*)&sA[kk][ty * 8];
            float4 a1 = *(const float4*)&sA[kk][ty * 8 + 4];
            const ull* wp2 = (const ull*)&sW[kk][tx * 4];
            ull w0 = wp2[0], w1 = wp2[1];
            ull ad[8];
            ad[0] = pack_dup(a0.x); ad[1] = pack_dup(a0.y);
            ad[2] = pack_dup(a0.z); ad[3] = pack_dup(a0.w);
            ad[4] = pack_dup(a1.x); ad[5] = pack_dup(a1.y);
            ad[6] = pack_dup(a1.z); ad[7] = pack_dup(a1.w);
#pragma unroll
            for (int j = 0; j < 8; j++) { ffma2(acc[j][0], ad[j], w0); ffma2(acc[j][1], ad[j], w1); }
        }
        __syncthreads();
    }

#pragma unroll
    for (int j = 0; j < 8; j++) {
        int bb = ty * 8 + j;
#pragma unroll
        for (int p = 0; p < 2; p++) {
            float2 v = unpack2(acc[j][p]);
            int n = n0 + tx * 4 + p * 2;
            size_t base = ((size_t)blockIdx.y * B + bb) * (size_t)N;
            *(float2*)&C[base + n] = v;
        }
    }
}

__global__ void k_scomb(const float* __restrict__ part, int N, int nsl,
                        const float* __restrict__ b1, const float* __restrict__ b2,
                        int act, float* __restrict__ dst, int ldd)
{
    int idx = blockIdx.x * blockDim.x + threadIdx.x;
    if (idx >= B * N) return;
    int b = idx / N, n = idx % N;
    float v = 0.f;
    if (b1) v += b1[n];
    if (b2) v += b2[n];
    for (int s = 0; s < nsl; s++) v += part[((size_t)s * B + b) * (size_t)N + n];
    if (act) v = tanhf(v);
    dst[(size_t)b * ldd + n] = v;
}

// ---------------- fused attention (single read of encoder_out) ----------------
__global__ __launch_bounds__(256) void k_attn(const float* __restrict__ enc)
{
    int b = blockIdx.y;
    int warp = threadIdx.x >> 5, lane = threadIdx.x & 31;
    int wg = blockIdx.x * 8 + warp;

    const float4* qp = (const float4*)(g_q + (size_t)b * HDIM);
    float4 qv[8];
#pragma unroll
    for (int j = 0; j < 8; j++) qv[j] = qp[j * 32 + lane];

    float4 av[8];
#pragma unroll
    for (int j = 0; j < 8; j++) av[j] = make_float4(0.f, 0.f, 0.f, 0.f);
    float m = -1e30f, l = 0.f;

    int s0 = wg * 32;
    for (int r = 0; r < 32; r++) {
        const float4* row = (const float4*)(enc + ((size_t)(s0 + r) * B + b) * HDIM);
        float4 e[8];
#pragma unroll
        for (int j = 0; j < 8; j++) e[j] = row[j * 32 + lane];
        float d = 0.f;
#pragma unroll
        for (int j = 0; j < 8; j++)
            d += e[j].x * qv[j].x + e[j].y * qv[j].y + e[j].z * qv[j].z + e[j].w * qv[j].w;
#pragma unroll
        for (int off = 16; off > 0; off >>= 1)
            d += __shfl_xor_sync(0xffffffffu, d, off);

        float mn  = fmaxf(m, d);
        float fac = __expf(m - mn);
        float p   = __expf(d - mn);
        l = l * fac + p;
        m = mn;
#pragma unroll
        for (int j = 0; j < 8; j++) {
            av[j].x = av[j].x * fac + p * e[j].x;
            av[j].y = av[j].y * fac + p * e[j].y;
            av[j].z = av[j].z * fac + p * e[j].z;
            av[j].w = av[j].w * fac + p * e[j].w;
        }
    }
    int pi = b * 64 + wg;
    if (lane == 0) { g_pm[pi] = m; g_pl[pi] = l; }
    float4* pa = (float4*)(g_pacc + (size_t)pi * HDIM);
#pragma unroll
    for (int j = 0; j < 8; j++) pa[j * 32 + lane] = av[j];
}

__global__ void k_attn_comb(const float* __restrict__ h0)
{
    int b = blockIdx.x, t = threadIdx.x;
    float M = -1e30f;
    for (int c = 0; c < 64; c++) M = fmaxf(M, g_pm[b * 64 + c]);
    float lsum = 0.f;
    float4 ctx = make_float4(0.f, 0.f, 0.f, 0.f);
    for (int c = 0; c < 64; c++) {
        float fac = __expf(g_pm[b * 64 + c] - M);
        lsum += fac * g_pl[b * 64 + c];
        float4 a = *(const float4*)(g_pacc + (size_t)(b * 64 + c) * HDIM + t * 4);
        ctx.x += fac * a.x; ctx.y += fac * a.y;
        ctx.z += fac * a.z; ctx.w += fac * a.w;
    }
    float inv = 1.f / lsum;
    float4* dA = (float4*)(g_catA + (size_t)b * 2 * HDIM);
    dA[t] = make_float4(ctx.x * inv, ctx.y * inv, ctx.z * inv, ctx.w * inv);
    const float4* h4 = (const float4*)(h0 + (size_t)b * HDIM);
    dA[256 + t] = h4[t];
}

__global__ void k_lstm(const float* __restrict__ c0, float* __restrict__ out)
{
    int b = blockIdx.x, t = threadIdx.x;
    const float* g = g_gates + (size_t)b * G4;
#pragma unroll
    for (int c = 0; c < 4; c++) {
        int h = t * 4 + c;
        float gi = g[h], gf = g[HDIM + h], gg = g[2 * HDIM + h], go = g[3 * HDIM + h];
        float si = 1.f / (1.f + __expf(-gi));
        float sf = 1.f / (1.f + __expf(-gf));
        float so = 1.f / (1.f + __expf(-go));
        float cn = sf * c0[(size_t)b * HDIM + h] + si * tanhf(gg);
        float hn = so * tanhf(cn);
        g_hN[(size_t)b * HDIM + h] = hn;
        out[(size_t)B * VDIM + (size_t)b * HDIM + h] = hn;
        out[(size_t)B * VDIM + (size_t)B * HDIM + (size_t)b * HDIM + h] = cn;
    }
}

// ---------------- host launch ----------------
extern "C" void kernel_launch(void* const* d_in, const int* in_sizes, int n_in,
                              void* d_out, int out_size)
{
    const int*   tokens = (const int*)  d_in[0];
    const float* enc    = (const float*)d_in[1];
    const float* h0     = (const float*)d_in[2];
    const float* c0     = (const float*)d_in[3];
    const float* emb    = (const float*)d_in[4];
    const float* W_in   = (const float*)d_in[5];
    const float* W_out  = (const float*)d_in[6];
    const float* W_ih   = (const float*)d_in[7];
    const float* W_hh   = (const float*)d_in[8];
    const float* b_ih   = (const float*)d_in[9];
    const float* b_hh   = (const float*)d_in[10];
    const float* W_gen  = (const float*)d_in[11];
    const float* b_gen  = (const float*)d_in[12];
    float* out = (float*)d_out;

    float *part, *qbuf, *catA, *catB, *gates, *hN;
    cudaGetSymbolAddress((void**)&part,  g_part);
    cudaGetSymbolAddress((void**)&qbuf,  g_q);
    cudaGetSymbolAddress((void**)&catA,  g_catA);
    cudaGetSymbolAddress((void**)&catB,  g_catB);
    cudaGetSymbolAddress((void**)&gates, g_gates);
    cudaGetSymbolAddress((void**)&hN,    g_hN);

    const int SMH = 65536;
    cudaFuncSetAttribute(k_hmma, cudaFuncAttributeMaxDynamicSharedMemorySize, SMH);

    // embedding gather
    k_embed<<<B, 128>>>(tokens, emb);

    // q = h0 @ W_in  (W_in [K,N] n-major), split-K 16 on fp32 path
    k_gemm_nk<<<dim3(8, 16), 256>>>(h0, HDIM, W_in, HDIM, part, HDIM, HDIM, 16);
    k_scomb<<<(B * HDIM + 255) / 256, 256>>>(part, HDIM, 16, nullptr, nullptr, 0, qbuf, HDIM);

    // fused single-pass attention
    k_attn<<<dim3(8, B), 256>>>(enc);
    k_attn_comb<<<B, 256>>>(h0);

    // ctx_hat = tanh(catA @ W_out^T) -> catB[:, 0:H]  (HMMA, split-K 8)
    k_hmma<<<dim3(HDIM / 64, 8), 256, SMH>>>(catA, 2 * HDIM, W_out,
                                             nullptr, 0, nullptr,
                                             nullptr, 0, HDIM, 8,
                                             nullptr, nullptr, 0, part);
    k_scomb<<<(B * HDIM + 255) / 256, 256>>>(part, HDIM, 8, nullptr, nullptr, 1, catB, KCAT);

    // gates = catB @ W_ih^T + h0 @ W_hh^T + b_ih + b_hh  (HMMA dual, split-K 2)
    k_hmma<<<dim3(G4 / 64, 2), 256, SMH>>>(catB, KCAT, W_ih,
                                           h0, HDIM, W_hh,
                                           nullptr, 0, G4, 2,
                                           nullptr, nullptr, 0, part);
    k_scomb<<<(B * G4 + 255) / 256, 256>>>(part, G4, 2, b_ih, b_hh, 0, gates, G4);

    // LSTM cell -> hN, cN
    k_lstm<<<B, 256>>>(c0, out);

    // logits = hN @ W_gen^T + b_gen  (HMMA, direct, 364 CTAs @ 2/SM)
    k_hmma<<<dim3((VDIM + 63) / 64, 1), 256, SMH>>>(hN, HDIM, W_gen,
                                                    nullptr, 0, nullptr,
                                                    out, VDIM, VDIM, 1,
                                                    b_gen, nullptr, 0, nullptr);
}